// round 4
// baseline (speedup 1.0000x reference)
#include <cuda_runtime.h>
#include <cstdint>

#define NREL 500
#define NB   4096
#define DIM  256

// ---------------- device scratch (no allocations allowed) ----------------
__device__ int g_counts[NREL];
__device__ int g_offsets[NREL + 1];
__device__ int g_cursor[NREL];
__device__ int g_bucket[NB];
__device__ int g_stride;   // 1 = int32 relation ids, 2 = int64 (read low word)

// ---------------- dtype detect + zero ----------------
// If relation_type is int64 (values < 500, little-endian), every odd int32
// slot is the zero high word. If int32, odd slots hold live values
// (P(all 32 sampled odd slots == 0) ~ 500^-32 ~ 0).
__global__ void k_detect_zero(const int* __restrict__ rel32) {
    int t = threadIdx.x;
    if (t < NREL) g_counts[t] = 0;
    __syncthreads();
    if (t < 32) {
        unsigned ballot = __ballot_sync(0xFFFFFFFFu, rel32[2 * t + 1] != 0);
        if (t == 0) g_stride = (ballot != 0u) ? 1 : 2;
    }
}

__global__ void k_hist(const int* __restrict__ rel32) {
    int i = blockIdx.x * blockDim.x + threadIdx.x;
    if (i < NB) {
        int r = rel32[i * g_stride];
        r = max(0, min(NREL - 1, r));   // defensive clamp: never wild-atomic
        atomicAdd(&g_counts[r], 1);
    }
}

__global__ void k_scan() {
    __shared__ int sc[512];
    int t = threadIdx.x;
    int c = (t < NREL) ? g_counts[t] : 0;
    sc[t] = c;
    for (int off = 1; off < 512; off <<= 1) {
        __syncthreads();
        int v = (t >= off) ? sc[t - off] : 0;
        __syncthreads();
        sc[t] += v;
    }
    __syncthreads();
    if (t < NREL) {
        g_offsets[t + 1] = sc[t];
        g_cursor[t] = sc[t] - c;   // exclusive start
    }
    if (t == 0) g_offsets[0] = 0;
}

__global__ void k_scatter(const int* __restrict__ rel32) {
    int i = blockIdx.x * blockDim.x + threadIdx.x;
    if (i < NB) {
        int r = rel32[i * g_stride];
        r = max(0, min(NREL - 1, r));
        int p = atomicAdd(&g_cursor[r], 1);
        g_bucket[p] = i;
    }
}

// ---------------- packed f32x2 FMA (FFMA2) ----------------
__device__ __forceinline__ unsigned long long ffma2(unsigned long long acc, float a,
                                                    unsigned long long m) {
    unsigned long long aa, r;
    asm("mov.b64 %0, {%1, %1};" : "=l"(aa) : "f"(a));
    asm("fma.rn.f32x2 %0, %1, %2, %3;" : "=l"(r) : "l"(aa), "l"(m), "l"(acc));
    return r;
}

// Each thread owns 2 output columns (c = tid&127 -> cols 2c,2c+1) and NS samples
// of its subset. Matrix streamed from global (LDG.64, coalesced 1KB/row),
// embeddings broadcast from SMEM as float4.
template <int NS>
__device__ __forceinline__ void compute_store(const float* __restrict__ M,
                                              const float* __restrict__ se,
                                              float* __restrict__ out,
                                              int jbase, int sub_count, int c) {
    unsigned long long acc[NS];
#pragma unroll
    for (int s = 0; s < NS; ++s) acc[s] = 0ull;

    const unsigned long long* __restrict__ Mp =
        reinterpret_cast<const unsigned long long*>(M) + c;  // 128 u64 per row
    const float4* __restrict__ E = reinterpret_cast<const float4*>(se);

    for (int d4 = 0; d4 < 64; ++d4) {
        unsigned long long m0 = Mp[(4 * d4 + 0) * 128];
        unsigned long long m1 = Mp[(4 * d4 + 1) * 128];
        unsigned long long m2 = Mp[(4 * d4 + 2) * 128];
        unsigned long long m3 = Mp[(4 * d4 + 3) * 128];
#pragma unroll
        for (int s = 0; s < NS; ++s) {
            float4 e = E[s * 64 + d4];   // SMEM broadcast within subset
            acc[s] = ffma2(acc[s], e.x, m0);
            acc[s] = ffma2(acc[s], e.y, m1);
            acc[s] = ffma2(acc[s], e.z, m2);
            acc[s] = ffma2(acc[s], e.w, m3);
        }
    }
#pragma unroll
    for (int s = 0; s < NS; ++s) {
        if (s < sub_count) {
            int idx = g_bucket[jbase + s];
            *reinterpret_cast<unsigned long long*>(out + (size_t)idx * DIM + 2 * c) = acc[s];
        }
    }
}

// ---------------- main kernel: one CTA per relation ----------------
__global__ void __launch_bounds__(256) k_main(const float* __restrict__ emb,
                                              const float* __restrict__ mats,
                                              float* __restrict__ out) {
    __shared__ float s_emb[32 * DIM];   // 32 KB

    int r = blockIdx.x;
    int begin = g_offsets[r];
    int end   = g_offsets[r + 1];
    if (begin == end) return;

    const float* M = mats + (size_t)r * DIM * DIM;
    int tid = threadIdx.x;
    int g = tid >> 7;        // subset 0/1 (16 samples each)
    int c = tid & 127;       // column pair

    for (int base = begin; base < end; base += 32) {
        int n = min(32, end - base);
        // Stage up to 32 embeddings into SMEM, zero-padded.
        for (int i = tid; i < 32 * DIM; i += 256) {
            int s = i >> 8;
            float v = 0.0f;
            if (s < n) v = emb[(size_t)g_bucket[base + s] * DIM + (i & 255)];
            s_emb[i] = v;
        }
        __syncthreads();

        int sub = n - g * 16;
        sub = max(0, min(16, sub));
        int nsr = (sub + 3) & ~3;               // pad to multiple of 4
        const float* se = s_emb + g * 16 * DIM;
        int jbase = base + g * 16;

        switch (nsr) {
            case 4:  compute_store<4 >(M, se, out, jbase, sub, c); break;
            case 8:  compute_store<8 >(M, se, out, jbase, sub, c); break;
            case 12: compute_store<12>(M, se, out, jbase, sub, c); break;
            case 16: compute_store<16>(M, se, out, jbase, sub, c); break;
            default: break;  // empty subset
        }
        __syncthreads();
    }
}

// ---------------- launch ----------------
extern "C" void kernel_launch(void* const* d_in, const int* in_sizes, int n_in,
                              void* d_out, int out_size) {
    const float* emb = nullptr;
    const int* rel = nullptr;
    const float* mats = nullptr;

    // Identify inputs by element count (robust to metadata ordering).
    for (int i = 0; i < n_in; ++i) {
        if (in_sizes[i] == NB)                     rel  = (const int*)d_in[i];
        else if (in_sizes[i] == NB * DIM)          emb  = (const float*)d_in[i];
        else if (in_sizes[i] == NREL * DIM * DIM)  mats = (const float*)d_in[i];
    }
    // Fallback: positional order per reference signature (embedding, relation_type, relation_matrices)
    if (!emb  && n_in > 0) emb  = (const float*)d_in[0];
    if (!rel  && n_in > 1) rel  = (const int*)d_in[1];
    if (!mats && n_in > 2) mats = (const float*)d_in[2];

    float* out = (float*)d_out;

    k_detect_zero<<<1, 512>>>(rel);
    k_hist<<<(NB + 255) / 256, 256>>>(rel);
    k_scan<<<1, 512>>>();
    k_scatter<<<(NB + 255) / 256, 256>>>(rel);
    k_main<<<NREL, 256>>>(emb, mats, out);
}